// round 1
// baseline (speedup 1.0000x reference)
#include <cuda_runtime.h>

// ResnetBlock: out = x + grouped_conv1x1(relu(groupnorm(x)))
// B=8, D=256, T=32768, conv groups=8 (32ch each), GN groups=32 (8ch each).
// Each conv group contains exactly 4 GN subgroups -> fully self-contained
// per (b, conv-group, t) column.
//
// Strategy: one thread handles one (b, g) column at 2 consecutive t positions,
// everything packed as f32x2 (Blackwell packed fp32 pipe) to halve FFMA count.

#define T_LEN   32768
#define D_CH    256
#define NGROUPS 8
#define CPG     32      // channels per conv group
#define GN_SUB  4       // GN subgroups per conv group (8 channels each)
#define EPS_GN  1e-5f

// ---- packed f32x2 helpers (PTX-only instructions on sm_100+) ----
union F2U { float2 f; unsigned long long u; };

__device__ __forceinline__ float2 f2fma(float2 a, float2 b, float2 c) {
    F2U A, Bv, C, Dv; A.f = a; Bv.f = b; C.f = c;
    asm("fma.rn.f32x2 %0, %1, %2, %3;"
        : "=l"(Dv.u) : "l"(A.u), "l"(Bv.u), "l"(C.u));
    return Dv.f;
}
__device__ __forceinline__ float2 f2add(float2 a, float2 b) {
    F2U A, Bv, Dv; A.f = a; Bv.f = b;
    asm("add.rn.f32x2 %0, %1, %2;" : "=l"(Dv.u) : "l"(A.u), "l"(Bv.u));
    return Dv.f;
}
__device__ __forceinline__ float2 f2mul(float2 a, float2 b) {
    F2U A, Bv, Dv; A.f = a; Bv.f = b;
    asm("mul.rn.f32x2 %0, %1, %2;" : "=l"(Dv.u) : "l"(A.u), "l"(Bv.u));
    return Dv.f;
}

__global__ void __launch_bounds__(128)
rb_gn_conv_kernel(const float* __restrict__ x,
                  const float* __restrict__ gamma,
                  const float* __restrict__ beta,
                  const float* __restrict__ w,
                  float* __restrict__ out)
{
    __shared__ float2 wsm[CPG][CPG];   // duplicated weights: wsm[o][i] = {w,w}
    __shared__ float4 gbsm[CPG];       // {gamma,gamma,beta,beta} per channel

    const int g = blockIdx.y;
    const int b = blockIdx.z;
    const int tid = threadIdx.x;

    // ---- stage weights (dup both halves so LDS.128 feeds FFMA2 directly) ----
    {
        const float4* wg = (const float4*)(w + (size_t)g * CPG * CPG);
        #pragma unroll
        for (int k = tid; k < (CPG * CPG) / 4; k += 128) {
            float4 v = wg[k];
            int base = k * 4;            // flat o*32 + i, i%4==0 -> same row
            int o = base >> 5;
            int i = base & 31;
            wsm[o][i + 0] = make_float2(v.x, v.x);
            wsm[o][i + 1] = make_float2(v.y, v.y);
            wsm[o][i + 2] = make_float2(v.z, v.z);
            wsm[o][i + 3] = make_float2(v.w, v.w);
        }
        if (tid < CPG) {
            float ga = gamma[g * CPG + tid];
            float be = beta[g * CPG + tid];
            gbsm[tid] = make_float4(ga, ga, be, be);
        }
    }
    __syncthreads();

    const int t0 = (blockIdx.x * 128 + tid) * 2;
    const size_t col = ((size_t)(b * D_CH + g * CPG)) * T_LEN + t0;
    const float* xp = x + col;

    // ---- load 32 channels x 2 t into registers ----
    float2 xr[CPG];
    #pragma unroll
    for (int c = 0; c < CPG; ++c)
        xr[c] = *(const float2*)(xp + (size_t)c * T_LEN);

    // ---- groupnorm (4 subgroups of 8 channels) + affine + relu, packed ----
    float2 h[CPG];
    #pragma unroll
    for (int sg = 0; sg < GN_SUB; ++sg) {
        const int cb = sg * 8;
        float2 s = xr[cb];
        float2 q = f2mul(xr[cb], xr[cb]);
        #pragma unroll
        for (int j = 1; j < 8; ++j) {
            s = f2add(s, xr[cb + j]);
            q = f2fma(xr[cb + j], xr[cb + j], q);
        }
        float2 mean; mean.x = s.x * 0.125f; mean.y = s.y * 0.125f;
        // unbiased var = (sum(x^2) - sum*mean) / 7
        float2 var;
        var.x = (q.x - s.x * mean.x) * (1.0f / 7.0f);
        var.y = (q.y - s.y * mean.y) * (1.0f / 7.0f);
        float2 rstd;
        rstd.x = rsqrtf(var.x + EPS_GN);
        rstd.y = rsqrtf(var.y + EPS_GN);
        float2 nmr;   // -mean * rstd
        nmr.x = -mean.x * rstd.x;
        nmr.y = -mean.y * rstd.y;
        #pragma unroll
        for (int j = 0; j < 8; ++j) {
            const int c = cb + j;
            float4 gb = gbsm[c];
            float2 n = f2fma(xr[c], rstd, nmr);           // (x-mean)*rstd
            n = f2fma(n, make_float2(gb.x, gb.y), make_float2(gb.z, gb.w));
            h[c].x = fmaxf(n.x, 0.0f);
            h[c].y = fmaxf(n.y, 0.0f);
        }
    }

    // ---- 32x32 grouped matvec with residual (acc starts at x) ----
    float* op = out + col;
    #pragma unroll
    for (int o = 0; o < CPG; ++o) {
        float2 acc = xr[o];
        const float4* wrow = (const float4*)&wsm[o][0];  // 2 dup-weights / ld
        #pragma unroll
        for (int i = 0; i < CPG / 2; ++i) {
            float4 wv = wrow[i];
            acc = f2fma(h[2 * i + 0], make_float2(wv.x, wv.y), acc);
            acc = f2fma(h[2 * i + 1], make_float2(wv.z, wv.w), acc);
        }
        *(float2*)(op + (size_t)o * T_LEN) = acc;
    }
}

extern "C" void kernel_launch(void* const* d_in, const int* in_sizes, int n_in,
                              void* d_out, int out_size)
{
    const float* x     = (const float*)d_in[0];
    const float* gamma = (const float*)d_in[1];
    const float* beta  = (const float*)d_in[2];
    const float* w     = (const float*)d_in[3];
    float* out = (float*)d_out;

    const int bsz = in_sizes[0] / (D_CH * T_LEN);
    dim3 grid(T_LEN / 256, NGROUPS, bsz);   // 128 threads x 2 t = 256 t/block
    rb_gn_conv_kernel<<<grid, 128>>>(x, gamma, beta, w, out);
}

// round 2
// speedup vs baseline: 1.2037x; 1.2037x over previous
#include <cuda_runtime.h>

// ResnetBlock: out = x + grouped_conv1x1(relu(groupnorm(x)))
// B=8, D=256, T=32768, conv groups=8 (32ch), GN groups=32 (8ch).
//
// R1: matvec packed ACROSS INPUT-CHANNEL PAIRS (not across t), so raw
// contiguous weights feed fma.f32x2 directly — no duplicated-weight smem,
// half the LDS.128 traffic (L1 was 94.9% bound in R0).

#define T_LEN   32768
#define D_CH    256
#define NGROUPS 8
#define CPG     32
#define EPS_GN  1e-5f

union F2U { float2 f; unsigned long long u; };

__device__ __forceinline__ float2 f2fma(float2 a, float2 b, float2 c) {
    F2U A, Bv, C, Dv; A.f = a; Bv.f = b; C.f = c;
    asm("fma.rn.f32x2 %0, %1, %2, %3;"
        : "=l"(Dv.u) : "l"(A.u), "l"(Bv.u), "l"(C.u));
    return Dv.f;
}
__device__ __forceinline__ float2 f2add(float2 a, float2 b) {
    F2U A, Bv, Dv; A.f = a; Bv.f = b;
    asm("add.rn.f32x2 %0, %1, %2;" : "=l"(Dv.u) : "l"(A.u), "l"(Bv.u));
    return Dv.f;
}
__device__ __forceinline__ float2 f2mul(float2 a, float2 b) {
    F2U A, Bv, Dv; A.f = a; Bv.f = b;
    asm("mul.rn.f32x2 %0, %1, %2;" : "=l"(Dv.u) : "l"(A.u), "l"(Bv.u));
    return Dv.f;
}

__global__ void __launch_bounds__(128, 3)
rb_gn_conv_kernel(const float* __restrict__ x,
                  const float* __restrict__ gamma,
                  const float* __restrict__ beta,
                  const float* __restrict__ w,
                  float* __restrict__ out)
{
    __shared__ float4 wsm[CPG][CPG / 4];   // raw weights: wsm[o][i4] = 4 w's
    __shared__ float4 gbsm[CPG];           // {g,g,b,b} per channel

    const int g = blockIdx.y;
    const int b = blockIdx.z;
    const int tid = threadIdx.x;

    // straight contiguous copy of this group's 32x32 weights
    {
        const float4* wg = (const float4*)(w + (size_t)g * CPG * CPG);
        #pragma unroll
        for (int k = tid; k < (CPG * CPG) / 4; k += 128)
            ((float4*)wsm)[k] = wg[k];
        if (tid < CPG) {
            float ga = gamma[g * CPG + tid];
            float be = beta[g * CPG + tid];
            gbsm[tid] = make_float4(ga, ga, be, be);
        }
    }
    __syncthreads();

    const int t0 = (blockIdx.x * 128 + tid) * 2;
    const size_t col = ((size_t)(b * D_CH + g * CPG)) * T_LEN + t0;
    const float* xp = x + col;

    // ---- load 32 channels x 2 t ----
    float2 xr[CPG];
    #pragma unroll
    for (int c = 0; c < CPG; ++c)
        xr[c] = *(const float2*)(xp + (size_t)c * T_LEN);

    // ---- groupnorm + relu; emit h transposed into channel-pairs:
    //      hp0[q] = {h_{2q}(t0), h_{2q+1}(t0)},  hp1[q] = same at t1 ----
    float2 hp0[CPG / 2], hp1[CPG / 2];
    #pragma unroll
    for (int sg = 0; sg < 4; ++sg) {
        const int cb = sg * 8;
        float2 s = xr[cb];
        float2 q = f2mul(xr[cb], xr[cb]);
        #pragma unroll
        for (int j = 1; j < 8; ++j) {
            s = f2add(s, xr[cb + j]);
            q = f2fma(xr[cb + j], xr[cb + j], q);
        }
        float2 mean = make_float2(s.x * 0.125f, s.y * 0.125f);
        float2 var;
        var.x = (q.x - s.x * mean.x) * (1.0f / 7.0f);
        var.y = (q.y - s.y * mean.y) * (1.0f / 7.0f);
        float2 rstd = make_float2(rsqrtf(var.x + EPS_GN),
                                  rsqrtf(var.y + EPS_GN));
        float2 nmr = make_float2(-mean.x * rstd.x, -mean.y * rstd.y);
        #pragma unroll
        for (int j = 0; j < 4; ++j) {      // channel pair (cb+2j, cb+2j+1)
            const int c0 = cb + 2 * j;
            float4 gb0 = gbsm[c0];
            float4 gb1 = gbsm[c0 + 1];
            float2 n0 = f2fma(xr[c0], rstd, nmr);
            float2 n1 = f2fma(xr[c0 + 1], rstd, nmr);
            n0 = f2fma(n0, make_float2(gb0.x, gb0.y), make_float2(gb0.z, gb0.w));
            n1 = f2fma(n1, make_float2(gb1.x, gb1.y), make_float2(gb1.z, gb1.w));
            n0.x = fmaxf(n0.x, 0.0f);  n0.y = fmaxf(n0.y, 0.0f);
            n1.x = fmaxf(n1.x, 0.0f);  n1.y = fmaxf(n1.y, 0.0f);
            hp0[sg * 4 + j] = make_float2(n0.x, n1.x);   // t0, chan pair
            hp1[sg * 4 + j] = make_float2(n0.y, n1.y);   // t1, chan pair
        }
    }

    // ---- 32x32 matvec, i-paired; residual seeded into acc ----
    float* op = out + col;
    #pragma unroll
    for (int o = 0; o < CPG; ++o) {
        float2 a0 = make_float2(xr[o].x, 0.0f);   // t0 accumulator (i-paired)
        float2 a1 = make_float2(xr[o].y, 0.0f);   // t1 accumulator
        const float4* row = wsm[o];
        #pragma unroll
        for (int i4 = 0; i4 < CPG / 4; ++i4) {
            float4 wv = row[i4];                   // 4 raw weights, 1 LDS.128
            float2 wA = make_float2(wv.x, wv.y);   // natural reg pair
            float2 wB = make_float2(wv.z, wv.w);
            a0 = f2fma(hp0[2 * i4 + 0], wA, a0);
            a1 = f2fma(hp1[2 * i4 + 0], wA, a1);
            a0 = f2fma(hp0[2 * i4 + 1], wB, a0);
            a1 = f2fma(hp1[2 * i4 + 1], wB, a1);
        }
        *(float2*)(op + (size_t)o * T_LEN) =
            make_float2(a0.x + a0.y, a1.x + a1.y);
    }
}

extern "C" void kernel_launch(void* const* d_in, const int* in_sizes, int n_in,
                              void* d_out, int out_size)
{
    const float* x     = (const float*)d_in[0];
    const float* gamma = (const float*)d_in[1];
    const float* beta  = (const float*)d_in[2];
    const float* w     = (const float*)d_in[3];
    float* out = (float*)d_out;

    const int bsz = in_sizes[0] / (D_CH * T_LEN);
    dim3 grid(T_LEN / 256, NGROUPS, bsz);   // 128 threads x 2 t = 256 t/block
    rb_gn_conv_kernel<<<grid, 128>>>(x, gamma, beta, w, out);
}